// round 11
// baseline (speedup 1.0000x reference)
#include <cuda_runtime.h>
#include <cuda_fp16.h>
#include <cstdint>

#define BN_EPS 1e-5f

constexpr int N_    = 32;   // points per polyline
constexpr int C_    = 9;    // input channels
constexpr int H_    = 64;   // hidden
constexpr int OUT_  = 128;
constexpr int SAWH  = 36;   // X tile row stride in half2-words -> conflict-free frags
constexpr int SPWH  = 12;   // P tile row stride in half2-words -> conflict-free
constexpr int SVH   = 36;   // row stride (half2 words) for [4][32] pooled / H4 mats

// -------- device scratch (no allocations allowed) --------
__device__ float    g_b0v[H_], g_b1v[H_], g_b2v[H_];
__device__ uint32_t g_W0h[512];         // folded Wpre (k padded to 16), fp16 B-frag
__device__ uint32_t g_W1h[2048];        // folded W1 low half  (k 0..63), fp16 B-frag
__device__ uint32_t g_W1hh[2048];       // folded W1 high half (k 64..127), fp16 B-frag
__device__ uint32_t g_W2h[2048];        // folded W2, fp16 B-frag
__device__ uint32_t g_W3h[2048];        // raw W3, fp16 B-frag
__device__ uint32_t g_W4h[4096];        // raw W4 [64][128], fp16 B-frag
__device__ int      g_mask4;            // 1 if mask elements are 4 bytes wide

__device__ __forceinline__ uint32_t packh2(float a, float b) {
    __half2 h = __floats2half2_rn(a, b);
    return *(uint32_t*)&h;
}
__device__ __forceinline__ uint32_t h2bits(__half2 v) { return *(uint32_t*)&v; }
__device__ __forceinline__ __half2  bits2h(uint32_t u) { return *(__half2*)&u; }

__device__ __forceinline__ void mma_f16(float& c0, float& c1, float& c2, float& c3,
                                        uint32_t a0, uint32_t a1, uint32_t a2, uint32_t a3,
                                        uint32_t b0, uint32_t b1) {
    asm volatile(
        "mma.sync.aligned.m16n8k16.row.col.f32.f16.f16.f32 "
        "{%0,%1,%2,%3},{%4,%5,%6,%7},{%8,%9},{%0,%1,%2,%3};\n"
        : "+f"(c0), "+f"(c1), "+f"(c2), "+f"(c3)
        : "r"(a0), "r"(a1), "r"(a2), "r"(a3), "r"(b0), "r"(b1));
}

#define BARP(id) asm volatile("bar.sync %0, %1;" :: "r"(id), "r"(64) : "memory")

// ============================================================
// Fold BN into weights, build fp16 B-fragment tables, sniff mask dtype.
// ============================================================
__global__ void fold_kernel(const float* __restrict__ Wpre,
                            const float* __restrict__ g0,  const float* __restrict__ b0,
                            const float* __restrict__ m0,  const float* __restrict__ v0,
                            const float* __restrict__ W1,
                            const float* __restrict__ g1,  const float* __restrict__ bb1,
                            const float* __restrict__ m1,  const float* __restrict__ v1,
                            const float* __restrict__ W2,
                            const float* __restrict__ g2,  const float* __restrict__ bb2,
                            const float* __restrict__ m2,  const float* __restrict__ v2,
                            const float* __restrict__ W3,
                            const float* __restrict__ W4,
                            const void*  __restrict__ mask)
{
    __shared__ float s0[H_], s1[H_], s2[H_];
    __shared__ unsigned red[3];
    const int tid = threadIdx.x;

    if (tid < 3) red[tid] = 0u;
    if (tid < H_) {
        float sc0 = g0[tid] * rsqrtf(v0[tid] + BN_EPS);
        float sc1 = g1[tid] * rsqrtf(v1[tid] + BN_EPS);
        float sc2 = g2[tid] * rsqrtf(v2[tid] + BN_EPS);
        s0[tid] = sc0; s1[tid] = sc1; s2[tid] = sc2;
        g_b0v[tid] = b0[tid]  - m0[tid] * sc0;
        g_b1v[tid] = bb1[tid] - m1[tid] * sc1;
        g_b2v[tid] = bb2[tid] - m2[tid] * sc2;
    }
    __syncthreads();

    // fp16 B-frag (m16n8k16): reg r holds half2 {W[k0][h], W[k0+1][h]},
    // k0 = kt*16 + (lane&3)*2 + r*8, h = n-tile*8 + (lane>>2)

    // Wpre (single k-step, C=9 zero-padded to 16)
    for (int i = tid; i < 512; i += blockDim.x) {
        int r = i & 1, lane = (i >> 1) & 31, t = (i >> 6) & 3, w = (i >> 8) & 1;
        int k0 = (lane & 3) * 2 + r * 8;
        int h  = w * 32 + t * 8 + (lane >> 2);
        float va = (k0     < C_) ? Wpre[k0 * H_ + h]       * s0[h] : 0.0f;
        float vb = (k0 + 1 < C_) ? Wpre[(k0 + 1) * H_ + h] * s0[h] : 0.0f;
        g_W0h[i] = packh2(va, vb);
    }

    // W1 (both halves), W2, W3: [64][64] fp16 frags (4 k-steps of 16)
    for (int i = tid; i < 2048; i += blockDim.x) {
        int r = i & 1, lane = (i >> 1) & 31, t = (i >> 6) & 3, kt = (i >> 8) & 3, w = (i >> 10) & 1;
        int k0 = kt * 16 + (lane & 3) * 2 + r * 8;
        int h  = w * 32 + t * 8 + (lane >> 2);
        g_W1h[i]  = packh2(W1[k0 * H_ + h] * s1[h],        W1[(k0 + 1) * H_ + h] * s1[h]);
        g_W1hh[i] = packh2(W1[(H_ + k0) * H_ + h] * s1[h], W1[(H_ + k0 + 1) * H_ + h] * s1[h]);
        g_W2h[i]  = packh2(W2[k0 * H_ + h] * s2[h],        W2[(k0 + 1) * H_ + h] * s2[h]);
        g_W3h[i]  = packh2(W3[k0 * H_ + h],                W3[(k0 + 1) * H_ + h]);
    }

    // W4 [64][128]: 4 k-steps x 16 n-tiles (fp16)
    for (int i = tid; i < 4096; i += blockDim.x) {
        int r = i & 1, lane = (i >> 1) & 31, tt = (i >> 6) & 15, kt = (i >> 10) & 3;
        int k0 = kt * 16 + (lane & 3) * 2 + r * 8;
        int o  = tt * 8 + (lane >> 2);
        g_W4h[i] = packh2(W4[k0 * OUT_ + o], W4[(k0 + 1) * OUT_ + o]);
    }

    // Parallel mask dtype sniff (first 1024 bytes).
    {
        const unsigned char* mb = (const unsigned char*)mask;
        unsigned mx = 0, off = 0, al = 0;
        for (int i = tid * 4; i < tid * 4 + 4; i++) {
            unsigned v = mb[i];
            mx |= v;
            if ((i & 3) != 0) off |= v; else al |= v;
        }
        atomicOr(&red[0], mx);
        atomicOr(&red[1], off);
        atomicOr(&red[2], al);
        __syncthreads();
        if (tid == 0)
            g_mask4 = (red[0] > 1u) || (red[1] == 0u && red[2] != 0u);
    }
}

// ============================================================
// Fused encoder: 4 polylines per CTA, 256 threads (8 warps), all-fp16 mma.
// FULLY DECOUPLED polylines: warps {2p, 2p+1} run poly p end-to-end;
// every sync is a 64-thread named barrier (id 1+p). No __syncthreads.
// sT / W3 / W4 are per-warp M=16 mmas with only row 0 valid.
// ============================================================
__global__ __launch_bounds__(256, 4) void pnet_kernel(
    const float* __restrict__ poly,   // [NPOLY, N, C]
    const void*  __restrict__ mask,   // [NPOLY, N]
    const float* __restrict__ b3,     // [H]
    const float* __restrict__ b4,     // [OUT]
    float*       __restrict__ out,    // [NPOLY, OUT]
    int npoly)
{
    __shared__ __align__(16) uint32_t sA[4 * N_ * SAWH];  // X0 / X1 half2 per poly (in-place)
    __shared__ __align__(16) uint32_t sP[4 * N_ * SPWH];  // padded input half2
    __shared__ float    sM[4 * N_];
    __shared__ uint32_t sPool1h[4 * SVH];                  // pooled1 half2 words (h/2)
    __shared__ uint32_t sPool3h[4 * SVH];                  // pooled3 half2 words
    __shared__ uint32_t sH4h[4 * SVH];                     // relu(W3 out) half2 words
    __shared__ __align__(16) float sOut[4 * 132];
    __shared__ int      sValid[4];

    const int tid  = threadIdx.x;
    const int lane = tid & 31;
    const int wid  = tid >> 5;
    const int p    = wid >> 1;      // poly slot
    const int w    = wid & 1;       // h-half owned by this warp
    const int pid  = blockIdx.x * 4 + p;
    const int r0   = lane >> 2;
    const int c0   = lane & 3;
    const bool vp  = pid < npoly;
    const __half2 hz = __float2half2_rn(0.0f);

    uint32_t* const sAp = sA + p * (N_ * SAWH);
    uint32_t* const sPp = sP + p * (N_ * SPWH);

    // ---------------- phase 0: load points (fp16, zero-padded k) + mask ----------------
    {
        const float* pp = poly + (size_t)pid * (N_ * C_);
        __half* sPh = (__half*)sPp;
        int q = w * 32 + lane;
        for (int i = q; i < N_ * 16; i += 64) {
            int n = i >> 4, c = i & 15;
            float v = (vp && c < C_) ? pp[n * C_ + c] : 0.0f;
            sPh[n * (2 * SPWH) + c] = __float2half_rn(v);
        }
        if (q < N_) {
            bool valid = false;
            if (vp) {
                size_t idx = (size_t)pid * N_ + q;
                valid = g_mask4 ? (((const unsigned*)mask)[idx] != 0u)
                                : (((const unsigned char*)mask)[idx] != 0u);
            }
            sM[p * N_ + q] = valid ? 1.0f : 0.0f;
            if (q == 0) sValid[p] = 0;
        }
    }
    BARP(1 + p);
    {
        int q = w * 32 + lane;
        if (q < N_ && sM[p * N_ + q] != 0.0f) sValid[p] = 1;  // benign: all store 1
    }

    float acc[2][4][4];
    float dj2, dj3;   // dummy sinks for row-0-only mmas

    // ---------------- stage 1: X0 = relu(P @ Wpre' + b0') * mask (1 k-step) ----------------
    {
        #pragma unroll
        for (int t = 0; t < 4; t++) {
            int hc = w * 32 + t * 8 + c0 * 2;
            float v0 = g_b0v[hc], v1 = g_b0v[hc + 1];
            #pragma unroll
            for (int m = 0; m < 2; m++) {
                acc[m][t][0] = v0; acc[m][t][1] = v1;
                acc[m][t][2] = v0; acc[m][t][3] = v1;
            }
        }
        uint32_t a[2][4];
        #pragma unroll
        for (int m = 0; m < 2; m++) {
            int base = (m * 16 + r0) * SPWH + c0;
            a[m][0] = sPp[base];
            a[m][1] = sPp[base + 8 * SPWH];
            a[m][2] = sPp[base + 4];
            a[m][3] = sPp[base + 8 * SPWH + 4];
        }
        const uint32_t* Wf = g_W0h + w * 256;
        #pragma unroll
        for (int t = 0; t < 4; t++) {
            uint2 b = *(const uint2*)(Wf + (t * 32 + lane) * 2);
            #pragma unroll
            for (int m = 0; m < 2; m++)
                mma_f16(acc[m][t][0], acc[m][t][1], acc[m][t][2], acc[m][t][3],
                        a[m][0], a[m][1], a[m][2], a[m][3], b.x, b.y);
        }
        // epilogue: relu*mask + store X0 + pool, all in half2
        uint32_t pm[4] = {0, 0, 0, 0};
        #pragma unroll
        for (int m = 0; m < 2; m++) {
            __half2 mk0 = __float2half2_rn(sM[p * N_ + m * 16 + r0]);
            __half2 mk1 = __float2half2_rn(sM[p * N_ + m * 16 + r0 + 8]);
            #pragma unroll
            for (int t = 0; t < 4; t++) {
                int wc = w * 16 + t * 4 + c0;
                int nb = (m * 16 + r0) * SAWH;
                __half2 a01 = __hmul2(__hmax2(__floats2half2_rn(acc[m][t][0], acc[m][t][1]), hz), mk0);
                __half2 a23 = __hmul2(__hmax2(__floats2half2_rn(acc[m][t][2], acc[m][t][3]), hz), mk1);
                sAp[nb + wc]            = h2bits(a01);
                sAp[nb + 8 * SAWH + wc] = h2bits(a23);
                pm[t] = h2bits(__hmax2(bits2h(pm[t]), __hmax2(a01, a23)));
            }
        }
        #pragma unroll
        for (int s = 4; s < 32; s <<= 1) {
            #pragma unroll
            for (int t = 0; t < 4; t++)
                pm[t] = h2bits(__hmax2(bits2h(pm[t]),
                                       bits2h(__shfl_xor_sync(0xFFFFFFFFu, pm[t], s))));
        }
        if (r0 == 0) {
            #pragma unroll
            for (int t = 0; t < 4; t++)
                sPool1h[p * SVH + w * 16 + t * 4 + c0] = pm[t];
        }
    }
    BARP(1 + p);   // X0 + pooled1 visible to the pair

    // ---------------- sT = b1' + pooled1 @ W1_hi (per-warp M=16 mma, row 0 valid) ----------------
    float tv0[4], tv1[4];   // broadcast stage-2 bias per tile
    {
        float t0[4] = {0, 0, 0, 0}, t1[4] = {0, 0, 0, 0};
        dj2 = 0.0f; dj3 = 0.0f;
        #pragma unroll
        for (int kt = 0; kt < 4; kt++) {
            uint32_t a0 = (r0 == 0) ? sPool1h[p * SVH + kt * 8 + c0]     : 0u;
            uint32_t a2 = (r0 == 0) ? sPool1h[p * SVH + kt * 8 + 4 + c0] : 0u;
            #pragma unroll
            for (int t = 0; t < 4; t++) {
                uint2 b = *(const uint2*)(g_W1hh + w * 1024 + ((kt * 4 + t) * 32 + lane) * 2);
                mma_f16(t0[t], t1[t], dj2, dj3, a0, 0u, a2, 0u, b.x, b.y);
            }
        }
        #pragma unroll
        for (int t = 0; t < 4; t++) {
            int hc = w * 32 + t * 8 + c0 * 2;
            tv0[t] = __shfl_sync(0xFFFFFFFFu, t0[t], c0) + g_b1v[hc];
            tv1[t] = __shfl_sync(0xFFFFFFFFu, t1[t], c0) + g_b1v[hc + 1];
        }
    }

    // ---------------- stage 2: X1 = relu(X0 @ W1_lo + t) * mask (in-place) ----------------
    {
        #pragma unroll
        for (int t = 0; t < 4; t++) {
            #pragma unroll
            for (int m = 0; m < 2; m++) {
                acc[m][t][0] = tv0[t]; acc[m][t][1] = tv1[t];
                acc[m][t][2] = tv0[t]; acc[m][t][3] = tv1[t];
            }
        }
        const uint32_t* Wf = g_W1h + w * 1024;
        #pragma unroll
        for (int kt = 0; kt < 4; kt++) {
            uint32_t a[2][4];
            #pragma unroll
            for (int m = 0; m < 2; m++) {
                int base = (m * 16 + r0) * SAWH + kt * 8 + c0;
                a[m][0] = sAp[base];
                a[m][1] = sAp[base + 8 * SAWH];
                a[m][2] = sAp[base + 4];
                a[m][3] = sAp[base + 8 * SAWH + 4];
            }
            #pragma unroll
            for (int t = 0; t < 4; t++) {
                uint2 b = *(const uint2*)(Wf + ((kt * 4 + t) * 32 + lane) * 2);
                #pragma unroll
                for (int m = 0; m < 2; m++)
                    mma_f16(acc[m][t][0], acc[m][t][1], acc[m][t][2], acc[m][t][3],
                            a[m][0], a[m][1], a[m][2], a[m][3], b.x, b.y);
            }
        }
    }
    BARP(1 + p);   // pair's reads of X0 complete before in-place X1 store
    {
        #pragma unroll
        for (int m = 0; m < 2; m++) {
            __half2 mk0 = __float2half2_rn(sM[p * N_ + m * 16 + r0]);
            __half2 mk1 = __float2half2_rn(sM[p * N_ + m * 16 + r0 + 8]);
            #pragma unroll
            for (int t = 0; t < 4; t++) {
                int wc = w * 16 + t * 4 + c0;
                int nb = (m * 16 + r0) * SAWH;
                sAp[nb + wc]            = h2bits(__hmul2(__hmax2(
                    __floats2half2_rn(acc[m][t][0], acc[m][t][1]), hz), mk0));
                sAp[nb + 8 * SAWH + wc] = h2bits(__hmul2(__hmax2(
                    __floats2half2_rn(acc[m][t][2], acc[m][t][3]), hz), mk1));
            }
        }
    }
    BARP(1 + p);   // X1 visible to the pair

    // ---------------- stage 3: relu(X1 @ W2 + b2') * mask -> pool (regs only) ----------------
    {
        #pragma unroll
        for (int t = 0; t < 4; t++) {
            int hc = w * 32 + t * 8 + c0 * 2;
            float v0 = g_b2v[hc], v1 = g_b2v[hc + 1];
            #pragma unroll
            for (int m = 0; m < 2; m++) {
                acc[m][t][0] = v0; acc[m][t][1] = v1;
                acc[m][t][2] = v0; acc[m][t][3] = v1;
            }
        }
        const uint32_t* Wf = g_W2h + w * 1024;
        #pragma unroll
        for (int kt = 0; kt < 4; kt++) {
            uint32_t a[2][4];
            #pragma unroll
            for (int m = 0; m < 2; m++) {
                int base = (m * 16 + r0) * SAWH + kt * 8 + c0;
                a[m][0] = sAp[base];
                a[m][1] = sAp[base + 8 * SAWH];
                a[m][2] = sAp[base + 4];
                a[m][3] = sAp[base + 8 * SAWH + 4];
            }
            #pragma unroll
            for (int t = 0; t < 4; t++) {
                uint2 b = *(const uint2*)(Wf + ((kt * 4 + t) * 32 + lane) * 2);
                #pragma unroll
                for (int m = 0; m < 2; m++)
                    mma_f16(acc[m][t][0], acc[m][t][1], acc[m][t][2], acc[m][t][3],
                            a[m][0], a[m][1], a[m][2], a[m][3], b.x, b.y);
            }
        }
        // epilogue: relu*mask -> pool via half2 + shfl (no X2 store)
        uint32_t pm[4] = {0, 0, 0, 0};
        #pragma unroll
        for (int m = 0; m < 2; m++) {
            __half2 mk0 = __float2half2_rn(sM[p * N_ + m * 16 + r0]);
            __half2 mk1 = __float2half2_rn(sM[p * N_ + m * 16 + r0 + 8]);
            #pragma unroll
            for (int t = 0; t < 4; t++) {
                __half2 a01 = __hmul2(__hmax2(__floats2half2_rn(acc[m][t][0], acc[m][t][1]), hz), mk0);
                __half2 a23 = __hmul2(__hmax2(__floats2half2_rn(acc[m][t][2], acc[m][t][3]), hz), mk1);
                pm[t] = h2bits(__hmax2(bits2h(pm[t]), __hmax2(a01, a23)));
            }
        }
        #pragma unroll
        for (int s = 4; s < 32; s <<= 1) {
            #pragma unroll
            for (int t = 0; t < 4; t++)
                pm[t] = h2bits(__hmax2(bits2h(pm[t]),
                                       bits2h(__shfl_xor_sync(0xFFFFFFFFu, pm[t], s))));
        }
        if (r0 == 0) {
            #pragma unroll
            for (int t = 0; t < 4; t++)
                sPool3h[p * SVH + w * 16 + t * 4 + c0] = pm[t];
        }
    }
    BARP(1 + p);   // pooled3 visible to the pair

    // ---------------- head part 1: H4 = relu(pooled3 @ W3 + b3) (per-warp M=16 mma) ----------------
    {
        float h0[4] = {0, 0, 0, 0}, h1[4] = {0, 0, 0, 0};
        dj2 = 0.0f; dj3 = 0.0f;
        #pragma unroll
        for (int kt = 0; kt < 4; kt++) {
            uint32_t a0 = (r0 == 0) ? sPool3h[p * SVH + kt * 8 + c0]     : 0u;
            uint32_t a2 = (r0 == 0) ? sPool3h[p * SVH + kt * 8 + 4 + c0] : 0u;
            #pragma unroll
            for (int t = 0; t < 4; t++) {
                uint2 b = *(const uint2*)(g_W3h + w * 1024 + ((kt * 4 + t) * 32 + lane) * 2);
                mma_f16(h0[t], h1[t], dj2, dj3, a0, 0u, a2, 0u, b.x, b.y);
            }
        }
        if (r0 == 0) {
            #pragma unroll
            for (int t = 0; t < 4; t++) {
                int hc = w * 32 + t * 8 + c0 * 2;
                sH4h[p * SVH + w * 16 + t * 4 + c0] =
                    packh2(fmaxf(h0[t] + b3[hc], 0.0f), fmaxf(h1[t] + b3[hc + 1], 0.0f));
            }
        }
    }
    BARP(1 + p);   // H4 visible to the pair

    // ---------------- head part 2: out = (H4 @ W4 + b4) * anyvalid (per-warp, 8 n-tiles) ----------------
    {
        float e0[8], e1[8];
        #pragma unroll
        for (int j = 0; j < 8; j++) { e0[j] = 0.0f; e1[j] = 0.0f; }
        dj2 = 0.0f; dj3 = 0.0f;
        #pragma unroll
        for (int kt = 0; kt < 4; kt++) {
            uint32_t a0 = (r0 == 0) ? sH4h[p * SVH + kt * 8 + c0]     : 0u;
            uint32_t a2 = (r0 == 0) ? sH4h[p * SVH + kt * 8 + 4 + c0] : 0u;
            #pragma unroll
            for (int j = 0; j < 8; j++) {
                int tt = w * 8 + j;
                uint2 b = *(const uint2*)(g_W4h + ((kt * 16 + tt) * 32 + lane) * 2);
                mma_f16(e0[j], e1[j], dj2, dj3, a0, 0u, a2, 0u, b.x, b.y);
            }
        }
        if (r0 == 0) {
            float vf = sValid[p] ? 1.0f : 0.0f;
            #pragma unroll
            for (int j = 0; j < 8; j++) {
                int o = (w * 8 + j) * 8 + c0 * 2;
                sOut[p * 132 + o]     = (e0[j] + b4[o])     * vf;
                sOut[p * 132 + o + 1] = (e1[j] + b4[o + 1]) * vf;
            }
        }
    }
    BARP(1 + p);   // sOut[p] complete

    // ---------------- pair-coalesced store: 64 threads x float2 ----------------
    if (vp) {
        int q = w * 32 + lane;
        float2 v = *(const float2*)(sOut + p * 132 + q * 2);
        *(float2*)(out + (size_t)pid * OUT_ + q * 2) = v;
    }
}

// ============================================================
// Launch
// ============================================================
extern "C" void kernel_launch(void* const* d_in, const int* in_sizes, int n_in,
                              void* d_out, int out_size)
{
    const float* poly = (const float*)d_in[0];
    const float* Wpre = (const float*)d_in[1];
    const float* g0   = (const float*)d_in[2];
    const float* b0   = (const float*)d_in[3];
    const float* m0   = (const float*)d_in[4];
    const float* v0   = (const float*)d_in[5];
    const float* W1   = (const float*)d_in[6];
    const float* g1   = (const float*)d_in[7];
    const float* bb1  = (const float*)d_in[8];
    const float* m1   = (const float*)d_in[9];
    const float* v1   = (const float*)d_in[10];
    const float* W2   = (const float*)d_in[11];
    const float* g2   = (const float*)d_in[12];
    const float* bb2  = (const float*)d_in[13];
    const float* m2   = (const float*)d_in[14];
    const float* v2   = (const float*)d_in[15];
    const float* W3   = (const float*)d_in[16];
    const float* b3   = (const float*)d_in[17];
    const float* W4   = (const float*)d_in[18];
    const float* b4   = (const float*)d_in[19];
    const void*  mask = d_in[20];

    const int npoly = in_sizes[0] / (N_ * C_);

    fold_kernel<<<1, 256>>>(Wpre, g0, b0, m0, v0,
                            W1, g1, bb1, m1, v1,
                            W2, g2, bb2, m2, v2, W3, W4, mask);
    pnet_kernel<<<(npoly + 3) / 4, 256>>>(poly, mask, b3, b4, (float*)d_out, npoly);
}

// round 12
// speedup vs baseline: 1.2986x; 1.2986x over previous
#include <cuda_runtime.h>
#include <cuda_fp16.h>
#include <cstdint>

#define BN_EPS 1e-5f

constexpr int N_    = 32;   // points per polyline
constexpr int C_    = 9;    // input channels
constexpr int H_    = 64;   // hidden
constexpr int OUT_  = 128;
constexpr int SAWH  = 36;   // X tile row stride in half2-words -> conflict-free frags
constexpr int SPWH  = 12;   // P tile row stride in half2-words -> conflict-free
constexpr int SVH   = 36;   // row stride (half2 words) for [4][32] pooled / H4 mats
constexpr int SVW   = 68;   // row stride (f32) for sT

// -------- device scratch (no allocations allowed) --------
__device__ float    g_b0v[H_], g_b1v[H_], g_b2v[H_];
__device__ uint32_t g_W0h[512];         // folded Wpre (k padded to 16), fp16 B-frag
__device__ uint32_t g_W1h[2048];        // folded W1 low half  (k 0..63), fp16 B-frag
__device__ uint32_t g_W1hh[2048];       // folded W1 high half (k 64..127), fp16 B-frag
__device__ uint32_t g_W2h[2048];        // folded W2, fp16 B-frag
__device__ uint32_t g_W3h[2048];        // raw W3, fp16 B-frag
__device__ uint32_t g_W4h[4096];        // raw W4 [64][128], fp16 B-frag
__device__ int      g_mask4;            // 1 if mask elements are 4 bytes wide

__device__ __forceinline__ uint32_t packh2(float a, float b) {
    __half2 h = __floats2half2_rn(a, b);
    return *(uint32_t*)&h;
}
__device__ __forceinline__ uint32_t h2bits(__half2 v) { return *(uint32_t*)&v; }
__device__ __forceinline__ __half2  bits2h(uint32_t u) { return *(__half2*)&u; }

__device__ __forceinline__ void mma_f16(float& c0, float& c1, float& c2, float& c3,
                                        uint32_t a0, uint32_t a1, uint32_t a2, uint32_t a3,
                                        uint32_t b0, uint32_t b1) {
    asm volatile(
        "mma.sync.aligned.m16n8k16.row.col.f32.f16.f16.f32 "
        "{%0,%1,%2,%3},{%4,%5,%6,%7},{%8,%9},{%0,%1,%2,%3};\n"
        : "+f"(c0), "+f"(c1), "+f"(c2), "+f"(c3)
        : "r"(a0), "r"(a1), "r"(a2), "r"(a3), "r"(b0), "r"(b1));
}

#define BARP(id) asm volatile("bar.sync %0, %1;" :: "r"(id), "r"(64) : "memory")

// ============================================================
// Fold BN into weights, build fp16 B-fragment tables, sniff mask dtype.
// ============================================================
__global__ void fold_kernel(const float* __restrict__ Wpre,
                            const float* __restrict__ g0,  const float* __restrict__ b0,
                            const float* __restrict__ m0,  const float* __restrict__ v0,
                            const float* __restrict__ W1,
                            const float* __restrict__ g1,  const float* __restrict__ bb1,
                            const float* __restrict__ m1,  const float* __restrict__ v1,
                            const float* __restrict__ W2,
                            const float* __restrict__ g2,  const float* __restrict__ bb2,
                            const float* __restrict__ m2,  const float* __restrict__ v2,
                            const float* __restrict__ W3,
                            const float* __restrict__ W4,
                            const void*  __restrict__ mask)
{
    __shared__ float s0[H_], s1[H_], s2[H_];
    __shared__ unsigned red[3];
    const int tid = threadIdx.x;

    if (tid < 3) red[tid] = 0u;
    if (tid < H_) {
        float sc0 = g0[tid] * rsqrtf(v0[tid] + BN_EPS);
        float sc1 = g1[tid] * rsqrtf(v1[tid] + BN_EPS);
        float sc2 = g2[tid] * rsqrtf(v2[tid] + BN_EPS);
        s0[tid] = sc0; s1[tid] = sc1; s2[tid] = sc2;
        g_b0v[tid] = b0[tid]  - m0[tid] * sc0;
        g_b1v[tid] = bb1[tid] - m1[tid] * sc1;
        g_b2v[tid] = bb2[tid] - m2[tid] * sc2;
    }
    __syncthreads();

    // fp16 B-frag (m16n8k16): reg r holds half2 {W[k0][h], W[k0+1][h]},
    // k0 = kt*16 + (lane&3)*2 + r*8, h = n-tile*8 + (lane>>2)

    // Wpre (single k-step, C=9 zero-padded to 16)
    for (int i = tid; i < 512; i += blockDim.x) {
        int r = i & 1, lane = (i >> 1) & 31, t = (i >> 6) & 3, w = (i >> 8) & 1;
        int k0 = (lane & 3) * 2 + r * 8;
        int h  = w * 32 + t * 8 + (lane >> 2);
        float va = (k0     < C_) ? Wpre[k0 * H_ + h]       * s0[h] : 0.0f;
        float vb = (k0 + 1 < C_) ? Wpre[(k0 + 1) * H_ + h] * s0[h] : 0.0f;
        g_W0h[i] = packh2(va, vb);
    }

    // W1 (both halves), W2, W3: [64][64] fp16 frags (4 k-steps of 16)
    for (int i = tid; i < 2048; i += blockDim.x) {
        int r = i & 1, lane = (i >> 1) & 31, t = (i >> 6) & 3, kt = (i >> 8) & 3, w = (i >> 10) & 1;
        int k0 = kt * 16 + (lane & 3) * 2 + r * 8;
        int h  = w * 32 + t * 8 + (lane >> 2);
        g_W1h[i]  = packh2(W1[k0 * H_ + h] * s1[h],        W1[(k0 + 1) * H_ + h] * s1[h]);
        g_W1hh[i] = packh2(W1[(H_ + k0) * H_ + h] * s1[h], W1[(H_ + k0 + 1) * H_ + h] * s1[h]);
        g_W2h[i]  = packh2(W2[k0 * H_ + h] * s2[h],        W2[(k0 + 1) * H_ + h] * s2[h]);
        g_W3h[i]  = packh2(W3[k0 * H_ + h],                W3[(k0 + 1) * H_ + h]);
    }

    // W4 [64][128]: 4 k-steps x 16 n-tiles (fp16)
    for (int i = tid; i < 4096; i += blockDim.x) {
        int r = i & 1, lane = (i >> 1) & 31, tt = (i >> 6) & 15, kt = (i >> 10) & 3;
        int k0 = kt * 16 + (lane & 3) * 2 + r * 8;
        int o  = tt * 8 + (lane >> 2);
        g_W4h[i] = packh2(W4[k0 * OUT_ + o], W4[(k0 + 1) * OUT_ + o]);
    }

    // Parallel mask dtype sniff (first 1024 bytes).
    {
        const unsigned char* mb = (const unsigned char*)mask;
        unsigned mx = 0, off = 0, al = 0;
        for (int i = tid * 4; i < tid * 4 + 4; i++) {
            unsigned v = mb[i];
            mx |= v;
            if ((i & 3) != 0) off |= v; else al |= v;
        }
        atomicOr(&red[0], mx);
        atomicOr(&red[1], off);
        atomicOr(&red[2], al);
        __syncthreads();
        if (tid == 0)
            g_mask4 = (red[0] > 1u) || (red[1] == 0u && red[2] != 0u);
    }
}

// ============================================================
// Fused encoder: 4 polylines per CTA, 256 threads (8 warps), all-fp16 mma.
// R7 structure, with sT GEMM overlapped against stage-2 mma:
// acc starts at 0; sT is added in the epilogue after a single merged
// __syncthreads (sT visibility + X0-read fence for in-place X1 store).
// ============================================================
__global__ __launch_bounds__(256, 4) void pnet_kernel(
    const float* __restrict__ poly,   // [NPOLY, N, C]
    const void*  __restrict__ mask,   // [NPOLY, N]
    const float* __restrict__ b3,     // [H]
    const float* __restrict__ b4,     // [OUT]
    float*       __restrict__ out,    // [NPOLY, OUT]
    int npoly)
{
    __shared__ __align__(16) uint32_t sA[4 * N_ * SAWH];  // X0 / X1 half2 per poly (in-place)
    __shared__ __align__(16) uint32_t sP[4 * N_ * SPWH];  // padded input half2
    __shared__ float    sM[4 * N_];
    __shared__ uint32_t sPool1h[4 * SVH];                  // pooled1 as half2 rows
    __shared__ float    sT[4 * SVW];
    __shared__ uint32_t sPool3h[4 * SVH];                  // pooled3 as half2 rows
    __shared__ uint32_t sH4h[4 * SVH];                     // relu(W3 out) as half2 rows
    __shared__ __align__(16) float sOut[4 * 132];
    __shared__ int      sValid[4];

    const int tid  = threadIdx.x;
    const int lane = tid & 31;
    const int wid  = tid >> 5;
    const int p    = wid >> 1;      // poly slot
    const int w    = wid & 1;       // h-half owned by this warp
    const int pid  = blockIdx.x * 4 + p;
    const int r0   = lane >> 2;
    const int c0   = lane & 3;
    const bool vp  = pid < npoly;
    const __half2 hz = __float2half2_rn(0.0f);

    uint32_t* const sAp = sA + p * (N_ * SAWH);
    uint32_t* const sPp = sP + p * (N_ * SPWH);

    // ---------------- phase 0: load points (fp16, zero-padded k) + mask ----------------
    {
        const float* pp = poly + (size_t)pid * (N_ * C_);
        __half* sPh = (__half*)sPp;
        int q = w * 32 + lane;
        for (int i = q; i < N_ * 16; i += 64) {
            int n = i >> 4, c = i & 15;
            float v = (vp && c < C_) ? pp[n * C_ + c] : 0.0f;
            sPh[n * (2 * SPWH) + c] = __float2half_rn(v);
        }
        if (q < N_) {
            bool valid = false;
            if (vp) {
                size_t idx = (size_t)pid * N_ + q;
                valid = g_mask4 ? (((const unsigned*)mask)[idx] != 0u)
                                : (((const unsigned char*)mask)[idx] != 0u);
            }
            sM[p * N_ + q] = valid ? 1.0f : 0.0f;
            if (q == 0) sValid[p] = 0;
        }
    }
    BARP(1 + p);
    {
        int q = w * 32 + lane;
        if (q < N_ && sM[p * N_ + q] != 0.0f) sValid[p] = 1;  // benign: all store 1
    }

    float acc[2][4][4];

    // ---------------- stage 1: X0 = relu(P @ Wpre' + b0') * mask (1 k-step) ----------------
    {
        #pragma unroll
        for (int t = 0; t < 4; t++) {
            int hc = w * 32 + t * 8 + c0 * 2;
            float v0 = g_b0v[hc], v1 = g_b0v[hc + 1];
            #pragma unroll
            for (int m = 0; m < 2; m++) {
                acc[m][t][0] = v0; acc[m][t][1] = v1;
                acc[m][t][2] = v0; acc[m][t][3] = v1;
            }
        }
        uint32_t a[2][4];
        #pragma unroll
        for (int m = 0; m < 2; m++) {
            int base = (m * 16 + r0) * SPWH + c0;
            a[m][0] = sPp[base];
            a[m][1] = sPp[base + 8 * SPWH];
            a[m][2] = sPp[base + 4];
            a[m][3] = sPp[base + 8 * SPWH + 4];
        }
        const uint32_t* Wf = g_W0h + w * 256;
        #pragma unroll
        for (int t = 0; t < 4; t++) {
            uint2 b = *(const uint2*)(Wf + (t * 32 + lane) * 2);
            #pragma unroll
            for (int m = 0; m < 2; m++)
                mma_f16(acc[m][t][0], acc[m][t][1], acc[m][t][2], acc[m][t][3],
                        a[m][0], a[m][1], a[m][2], a[m][3], b.x, b.y);
        }
        // epilogue: relu*mask + store X0 + pool, all in half2
        uint32_t pm[4] = {0, 0, 0, 0};
        #pragma unroll
        for (int m = 0; m < 2; m++) {
            __half2 mk0 = __float2half2_rn(sM[p * N_ + m * 16 + r0]);
            __half2 mk1 = __float2half2_rn(sM[p * N_ + m * 16 + r0 + 8]);
            #pragma unroll
            for (int t = 0; t < 4; t++) {
                int wc = w * 16 + t * 4 + c0;
                int nb = (m * 16 + r0) * SAWH;
                __half2 a01 = __hmul2(__hmax2(__floats2half2_rn(acc[m][t][0], acc[m][t][1]), hz), mk0);
                __half2 a23 = __hmul2(__hmax2(__floats2half2_rn(acc[m][t][2], acc[m][t][3]), hz), mk1);
                sAp[nb + wc]            = h2bits(a01);
                sAp[nb + 8 * SAWH + wc] = h2bits(a23);
                pm[t] = h2bits(__hmax2(bits2h(pm[t]), __hmax2(a01, a23)));
            }
        }
        #pragma unroll
        for (int s = 4; s < 32; s <<= 1) {
            #pragma unroll
            for (int t = 0; t < 4; t++)
                pm[t] = h2bits(__hmax2(bits2h(pm[t]),
                                       bits2h(__shfl_xor_sync(0xFFFFFFFFu, pm[t], s))));
        }
        if (r0 == 0) {
            #pragma unroll
            for (int t = 0; t < 4; t++)
                sPool1h[p * SVH + w * 16 + t * 4 + c0] = pm[t];
        }
    }
    __syncthreads();   // X0 + pooled1 visible CTA-wide

    // ---------------- sT = b1' + pooled1 @ W1_hi (fp16, M=4, all 8 warps) ----------------
    // Issued BEFORE stage-2 mma; no sync until after stage-2's mma block, so the
    // sT chain latency is hidden behind stage-2's 16 independent mmas.
    {
        const int tw = wid >> 2, tt4 = wid & 3;
        const int hc = wid * 8 + c0 * 2;
        float d0 = g_b1v[hc], d1 = g_b1v[hc + 1], d2 = 0.0f, d3 = 0.0f;
        #pragma unroll
        for (int kt = 0; kt < 4; kt++) {
            uint32_t a0 = 0, a2 = 0;
            if (r0 < 4) {
                a0 = sPool1h[r0 * SVH + kt * 8 + c0];
                a2 = sPool1h[r0 * SVH + kt * 8 + 4 + c0];
            }
            uint2 b = *(const uint2*)(g_W1hh + (((tw * 4 + kt) * 4 + tt4) * 32 + lane) * 2);
            mma_f16(d0, d1, d2, d3, a0, 0u, a2, 0u, b.x, b.y);
        }
        if (r0 < 4) {
            sT[r0 * SVW + hc]     = d0;
            sT[r0 * SVW + hc + 1] = d1;
        }
    }

    // ---------------- stage 2 mma: acc = X0 @ W1_lo (acc from 0; sT added in epilogue) ----------------
    {
        #pragma unroll
        for (int t = 0; t < 4; t++)
            #pragma unroll
            for (int m = 0; m < 2; m++) {
                acc[m][t][0] = 0.0f; acc[m][t][1] = 0.0f;
                acc[m][t][2] = 0.0f; acc[m][t][3] = 0.0f;
            }
        const uint32_t* Wf = g_W1h + w * 1024;
        #pragma unroll
        for (int kt = 0; kt < 4; kt++) {
            uint32_t a[2][4];
            #pragma unroll
            for (int m = 0; m < 2; m++) {
                int base = (m * 16 + r0) * SAWH + kt * 8 + c0;
                a[m][0] = sAp[base];
                a[m][1] = sAp[base + 8 * SAWH];
                a[m][2] = sAp[base + 4];
                a[m][3] = sAp[base + 8 * SAWH + 4];
            }
            #pragma unroll
            for (int t = 0; t < 4; t++) {
                uint2 b = *(const uint2*)(Wf + ((kt * 4 + t) * 32 + lane) * 2);
                #pragma unroll
                for (int m = 0; m < 2; m++)
                    mma_f16(acc[m][t][0], acc[m][t][1], acc[m][t][2], acc[m][t][3],
                            a[m][0], a[m][1], a[m][2], a[m][3], b.x, b.y);
            }
        }
    }
    __syncthreads();   // merged: sT visible + all X0 reads done (in-place store safe)

    // ---------------- stage 2 epilogue: X1 = relu(acc + sT) * mask (in-place) ----------------
    {
        float tv0[4], tv1[4];
        #pragma unroll
        for (int t = 0; t < 4; t++) {
            int hc = w * 32 + t * 8 + c0 * 2;
            tv0[t] = sT[p * SVW + hc];
            tv1[t] = sT[p * SVW + hc + 1];
        }
        #pragma unroll
        for (int m = 0; m < 2; m++) {
            __half2 mk0 = __float2half2_rn(sM[p * N_ + m * 16 + r0]);
            __half2 mk1 = __float2half2_rn(sM[p * N_ + m * 16 + r0 + 8]);
            #pragma unroll
            for (int t = 0; t < 4; t++) {
                int wc = w * 16 + t * 4 + c0;
                int nb = (m * 16 + r0) * SAWH;
                sAp[nb + wc]            = h2bits(__hmul2(__hmax2(
                    __floats2half2_rn(acc[m][t][0] + tv0[t], acc[m][t][1] + tv1[t]), hz), mk0));
                sAp[nb + 8 * SAWH + wc] = h2bits(__hmul2(__hmax2(
                    __floats2half2_rn(acc[m][t][2] + tv0[t], acc[m][t][3] + tv1[t]), hz), mk1));
            }
        }
    }
    BARP(1 + p);   // pair's X1 visible before stage 3

    // ---------------- stage 3: relu(X1 @ W2 + b2') * mask -> pool (regs only) ----------------
    {
        #pragma unroll
        for (int t = 0; t < 4; t++) {
            int hc = w * 32 + t * 8 + c0 * 2;
            float v0 = g_b2v[hc], v1 = g_b2v[hc + 1];
            #pragma unroll
            for (int m = 0; m < 2; m++) {
                acc[m][t][0] = v0; acc[m][t][1] = v1;
                acc[m][t][2] = v0; acc[m][t][3] = v1;
            }
        }
        const uint32_t* Wf = g_W2h + w * 1024;
        #pragma unroll
        for (int kt = 0; kt < 4; kt++) {
            uint32_t a[2][4];
            #pragma unroll
            for (int m = 0; m < 2; m++) {
                int base = (m * 16 + r0) * SAWH + kt * 8 + c0;
                a[m][0] = sAp[base];
                a[m][1] = sAp[base + 8 * SAWH];
                a[m][2] = sAp[base + 4];
                a[m][3] = sAp[base + 8 * SAWH + 4];
            }
            #pragma unroll
            for (int t = 0; t < 4; t++) {
                uint2 b = *(const uint2*)(Wf + ((kt * 4 + t) * 32 + lane) * 2);
                #pragma unroll
                for (int m = 0; m < 2; m++)
                    mma_f16(acc[m][t][0], acc[m][t][1], acc[m][t][2], acc[m][t][3],
                            a[m][0], a[m][1], a[m][2], a[m][3], b.x, b.y);
            }
        }
        // epilogue: relu*mask -> pool via half2 + shfl (no X2 store)
        uint32_t pm[4] = {0, 0, 0, 0};
        #pragma unroll
        for (int m = 0; m < 2; m++) {
            __half2 mk0 = __float2half2_rn(sM[p * N_ + m * 16 + r0]);
            __half2 mk1 = __float2half2_rn(sM[p * N_ + m * 16 + r0 + 8]);
            #pragma unroll
            for (int t = 0; t < 4; t++) {
                __half2 a01 = __hmul2(__hmax2(__floats2half2_rn(acc[m][t][0], acc[m][t][1]), hz), mk0);
                __half2 a23 = __hmul2(__hmax2(__floats2half2_rn(acc[m][t][2], acc[m][t][3]), hz), mk1);
                pm[t] = h2bits(__hmax2(bits2h(pm[t]), __hmax2(a01, a23)));
            }
        }
        #pragma unroll
        for (int s = 4; s < 32; s <<= 1) {
            #pragma unroll
            for (int t = 0; t < 4; t++)
                pm[t] = h2bits(__hmax2(bits2h(pm[t]),
                                       bits2h(__shfl_xor_sync(0xFFFFFFFFu, pm[t], s))));
        }
        if (r0 == 0) {
            #pragma unroll
            for (int t = 0; t < 4; t++)
                sPool3h[p * SVH + w * 16 + t * 4 + c0] = pm[t];
        }
    }
    __syncthreads();

    // ---------------- head part 1: H4 = relu(pooled3 @ W3 + b3)  (fp16, M=4) ----------------
    {
        const int tw = wid >> 2, tt4 = wid & 3;
        const int hc = wid * 8 + c0 * 2;
        float d0 = b3[hc], d1 = b3[hc + 1], d2 = 0.0f, d3 = 0.0f;
        #pragma unroll
        for (int kt = 0; kt < 4; kt++) {
            uint32_t a0 = 0, a2 = 0;
            if (r0 < 4) {
                a0 = sPool3h[r0 * SVH + kt * 8 + c0];
                a2 = sPool3h[r0 * SVH + kt * 8 + 4 + c0];
            }
            uint2 b = *(const uint2*)(g_W3h + (((tw * 4 + kt) * 4 + tt4) * 32 + lane) * 2);
            mma_f16(d0, d1, d2, d3, a0, 0u, a2, 0u, b.x, b.y);
        }
        if (r0 < 4)
            sH4h[r0 * SVH + wid * 4 + c0] = packh2(fmaxf(d0, 0.0f), fmaxf(d1, 0.0f));
    }
    __syncthreads();

    // ---------------- head part 2: out = (H4 @ W4 + b4) * anyvalid  (fp16, M=4, N=128) ----------------
    {
        const int tt0 = wid * 2;
        float e0[2], e1[2], e2[2], e3[2];
        #pragma unroll
        for (int j = 0; j < 2; j++) {
            int o = (tt0 + j) * 8 + c0 * 2;
            e0[j] = b4[o]; e1[j] = b4[o + 1]; e2[j] = 0.0f; e3[j] = 0.0f;
        }
        #pragma unroll
        for (int kt = 0; kt < 4; kt++) {
            uint32_t a0 = 0, a2 = 0;
            if (r0 < 4) {
                a0 = sH4h[r0 * SVH + kt * 8 + c0];
                a2 = sH4h[r0 * SVH + kt * 8 + 4 + c0];
            }
            #pragma unroll
            for (int j = 0; j < 2; j++) {
                uint2 b = *(const uint2*)(g_W4h + ((kt * 16 + tt0 + j) * 32 + lane) * 2);
                mma_f16(e0[j], e1[j], e2[j], e3[j], a0, 0u, a2, 0u, b.x, b.y);
            }
        }
        if (r0 < 4) {
            float vf = sValid[r0] ? 1.0f : 0.0f;
            #pragma unroll
            for (int j = 0; j < 2; j++) {
                int o = (tt0 + j) * 8 + c0 * 2;
                sOut[r0 * 132 + o]     = e0[j] * vf;
                sOut[r0 * 132 + o + 1] = e1[j] * vf;
            }
        }
    }
    __syncthreads();

    // ---------------- coalesced store ----------------
    if (tid < 128) {
        int pp = tid >> 5, j = tid & 31;
        int opid = blockIdx.x * 4 + pp;
        if (opid < npoly) {
            float4 v = *(const float4*)(sOut + pp * 132 + j * 4);
            *(float4*)(out + (size_t)opid * OUT_ + j * 4) = v;
        }
    }
}

// ============================================================
// Launch
// ============================================================
extern "C" void kernel_launch(void* const* d_in, const int* in_sizes, int n_in,
                              void* d_out, int out_size)
{
    const float* poly = (const float*)d_in[0];
    const float* Wpre = (const float*)d_in[1];
    const float* g0   = (const float*)d_in[2];
    const float* b0   = (const float*)d_in[3];
    const float* m0   = (const float*)d_in[4];
    const float* v0   = (const float*)d_in[5];
    const float* W1   = (const float*)d_in[6];
    const float* g1   = (const float*)d_in[7];
    const float* bb1  = (const float*)d_in[8];
    const float* m1   = (const float*)d_in[9];
    const float* v1   = (const float*)d_in[10];
    const float* W2   = (const float*)d_in[11];
    const float* g2   = (const float*)d_in[12];
    const float* bb2  = (const float*)d_in[13];
    const float* m2   = (const float*)d_in[14];
    const float* v2   = (const float*)d_in[15];
    const float* W3   = (const float*)d_in[16];
    const float* b3   = (const float*)d_in[17];
    const float* W4   = (const float*)d_in[18];
    const float* b4   = (const float*)d_in[19];
    const void*  mask = d_in[20];

    const int npoly = in_sizes[0] / (N_ * C_);

    fold_kernel<<<1, 256>>>(Wpre, g0, b0, m0, v0,
                            W1, g1, bb1, m1, v1,
                            W2, g2, bb2, m2, v2, W3, W4, mask);
    pnet_kernel<<<(npoly + 3) / 4, 256>>>(poly, mask, b3, b4, (float*)d_out, npoly);
}

// round 13
// speedup vs baseline: 1.3247x; 1.0201x over previous
#include <cuda_runtime.h>
#include <cuda_fp16.h>
#include <cstdint>

#define BN_EPS 1e-5f

constexpr int N_    = 32;   // points per polyline
constexpr int C_    = 9;    // input channels
constexpr int H_    = 64;   // hidden
constexpr int OUT_  = 128;
constexpr int PSTR  = 36;   // partial-pool row stride (half2 words)
constexpr int SVH   = 36;   // row stride (half2 words) for H4
constexpr int SVW   = 68;   // row stride (f32) for sT

// -------- device scratch (no allocations allowed) --------
__device__ float    g_b0v[H_], g_b1v[H_], g_b2v[H_];
__device__ uint32_t g_W0h[512];         // folded Wpre (k padded to 16), fp16 B-frag
__device__ uint32_t g_W1h[2048];        // folded W1 low half  (k 0..63), fp16 B-frag
__device__ uint32_t g_W1hh[2048];       // folded W1 high half (k 64..127), fp16 B-frag
__device__ uint32_t g_W2h[2048];        // folded W2, fp16 B-frag
__device__ uint32_t g_W3h[2048];        // raw W3, fp16 B-frag
__device__ uint32_t g_W4h[4096];        // raw W4 [64][128], fp16 B-frag
__device__ int      g_mask4;            // 1 if mask elements are 4 bytes wide

__device__ __forceinline__ uint32_t packh2(float a, float b) {
    __half2 h = __floats2half2_rn(a, b);
    return *(uint32_t*)&h;
}
__device__ __forceinline__ uint32_t h2bits(__half2 v) { return *(uint32_t*)&v; }
__device__ __forceinline__ __half2  bits2h(uint32_t u) { return *(__half2*)&u; }
__device__ __forceinline__ uint32_t hmax2b(uint32_t a, uint32_t b) {
    return h2bits(__hmax2(bits2h(a), bits2h(b)));
}

__device__ __forceinline__ void mma_f16(float& c0, float& c1, float& c2, float& c3,
                                        uint32_t a0, uint32_t a1, uint32_t a2, uint32_t a3,
                                        uint32_t b0, uint32_t b1) {
    asm volatile(
        "mma.sync.aligned.m16n8k16.row.col.f32.f16.f16.f32 "
        "{%0,%1,%2,%3},{%4,%5,%6,%7},{%8,%9},{%0,%1,%2,%3};\n"
        : "+f"(c0), "+f"(c1), "+f"(c2), "+f"(c3)
        : "r"(a0), "r"(a1), "r"(a2), "r"(a3), "r"(b0), "r"(b1));
}

// ============================================================
// Fold BN into weights, build fp16 B-fragment tables, sniff mask dtype.
// ============================================================
__global__ void fold_kernel(const float* __restrict__ Wpre,
                            const float* __restrict__ g0,  const float* __restrict__ b0,
                            const float* __restrict__ m0,  const float* __restrict__ v0,
                            const float* __restrict__ W1,
                            const float* __restrict__ g1,  const float* __restrict__ bb1,
                            const float* __restrict__ m1,  const float* __restrict__ v1,
                            const float* __restrict__ W2,
                            const float* __restrict__ g2,  const float* __restrict__ bb2,
                            const float* __restrict__ m2,  const float* __restrict__ v2,
                            const float* __restrict__ W3,
                            const float* __restrict__ W4,
                            const void*  __restrict__ mask)
{
    __shared__ float s0[H_], s1[H_], s2[H_];
    __shared__ unsigned red[3];
    const int tid = threadIdx.x;

    if (tid < 3) red[tid] = 0u;
    if (tid < H_) {
        float sc0 = g0[tid] * rsqrtf(v0[tid] + BN_EPS);
        float sc1 = g1[tid] * rsqrtf(v1[tid] + BN_EPS);
        float sc2 = g2[tid] * rsqrtf(v2[tid] + BN_EPS);
        s0[tid] = sc0; s1[tid] = sc1; s2[tid] = sc2;
        g_b0v[tid] = b0[tid]  - m0[tid] * sc0;
        g_b1v[tid] = bb1[tid] - m1[tid] * sc1;
        g_b2v[tid] = bb2[tid] - m2[tid] * sc2;
    }
    __syncthreads();

    // fp16 B-frag (m16n8k16): reg r holds half2 {W[k0][h], W[k0+1][h]},
    // k0 = kt*16 + (lane&3)*2 + r*8, h = n-tile*8 + (lane>>2)

    // Wpre (single k-step, C=9 zero-padded to 16)
    for (int i = tid; i < 512; i += blockDim.x) {
        int r = i & 1, lane = (i >> 1) & 31, t = (i >> 6) & 3, w = (i >> 8) & 1;
        int k0 = (lane & 3) * 2 + r * 8;
        int h  = w * 32 + t * 8 + (lane >> 2);
        float va = (k0     < C_) ? Wpre[k0 * H_ + h]       * s0[h] : 0.0f;
        float vb = (k0 + 1 < C_) ? Wpre[(k0 + 1) * H_ + h] * s0[h] : 0.0f;
        g_W0h[i] = packh2(va, vb);
    }

    // W1 (both halves), W2, W3: [64][64] fp16 frags (4 k-steps of 16)
    for (int i = tid; i < 2048; i += blockDim.x) {
        int r = i & 1, lane = (i >> 1) & 31, t = (i >> 6) & 3, kt = (i >> 8) & 3, w = (i >> 10) & 1;
        int k0 = kt * 16 + (lane & 3) * 2 + r * 8;
        int h  = w * 32 + t * 8 + (lane >> 2);
        g_W1h[i]  = packh2(W1[k0 * H_ + h] * s1[h],        W1[(k0 + 1) * H_ + h] * s1[h]);
        g_W1hh[i] = packh2(W1[(H_ + k0) * H_ + h] * s1[h], W1[(H_ + k0 + 1) * H_ + h] * s1[h]);
        g_W2h[i]  = packh2(W2[k0 * H_ + h] * s2[h],        W2[(k0 + 1) * H_ + h] * s2[h]);
        g_W3h[i]  = packh2(W3[k0 * H_ + h],                W3[(k0 + 1) * H_ + h]);
    }

    // W4 [64][128]: 4 k-steps x 16 n-tiles (fp16)
    for (int i = tid; i < 4096; i += blockDim.x) {
        int r = i & 1, lane = (i >> 1) & 31, tt = (i >> 6) & 15, kt = (i >> 10) & 3;
        int k0 = kt * 16 + (lane & 3) * 2 + r * 8;
        int o  = tt * 8 + (lane >> 2);
        g_W4h[i] = packh2(W4[k0 * OUT_ + o], W4[(k0 + 1) * OUT_ + o]);
    }

    // Parallel mask dtype sniff (first 1024 bytes).
    {
        const unsigned char* mb = (const unsigned char*)mask;
        unsigned mx = 0, off = 0, al = 0;
        for (int i = tid * 4; i < tid * 4 + 4; i++) {
            unsigned v = mb[i];
            mx |= v;
            if ((i & 3) != 0) off |= v; else al |= v;
        }
        atomicOr(&red[0], mx);
        atomicOr(&red[1], off);
        atomicOr(&red[2], al);
        __syncthreads();
        if (tid == 0)
            g_mask4 = (red[0] > 1u) || (red[1] == 0u && red[2] != 0u);
    }
}

// ============================================================
// Fused encoder, register-resident X chain.
// 4 polylines per CTA, 256 threads. Warp w of pair p owns point rows
// [16w, 16w+16) of poly p across ALL 64 h columns (m-split).
// C-fragment of each stage == A-fragment of the next -> X0/X1 never
// touch shared memory. Pools are per-warp partials max-combined inside
// the cooperative sT/W3 A-loads. Heads stay cooperative M=4.
// ============================================================
__global__ __launch_bounds__(256, 4) void pnet_kernel(
    const float* __restrict__ poly,   // [NPOLY, N, C]
    const void*  __restrict__ mask,   // [NPOLY, N]
    const float* __restrict__ b3,     // [H]
    const float* __restrict__ b4,     // [OUT]
    float*       __restrict__ out,    // [NPOLY, OUT]
    int npoly)
{
    __shared__ uint32_t sPool1h[8 * PSTR];   // per-warp partial pool1 [(p*2+w)][32]
    __shared__ uint32_t sPool3h[8 * PSTR];   // per-warp partial pool3
    __shared__ float    sT[4 * SVW];         // stage-2 bias vector per poly
    __shared__ uint32_t sH4h[4 * SVH];       // relu(W3 out) half2 words
    __shared__ __align__(16) float sOut[4 * 132];
    __shared__ int      sVal2[8];            // per-warp any-valid flags

    const int tid  = threadIdx.x;
    const int lane = tid & 31;
    const int wid  = tid >> 5;
    const int p    = wid >> 1;      // poly slot
    const int w    = wid & 1;       // row-half owned by this warp
    const int pid  = blockIdx.x * 4 + p;
    const int r0   = lane >> 2;
    const int c0   = lane & 3;
    const bool vp  = pid < npoly;
    const __half2 hz = __float2half2_rn(0.0f);

    // ---------------- phase 0: points + mask straight into registers ----------------
    // rows owned by this thread: row0 = 16w + r0, row1 = row0 + 8
    uint32_t pa0, pa1, pa2, pa3;    // stage-1 A fragment (C padded to 16)
    float mk0f = 0.0f, mk1f = 0.0f;
    {
        float p00 = 0, p01 = 0, p10 = 0, p11 = 0, p08 = 0, p18 = 0;
        if (vp) {
            const float* pr0 = poly + (size_t)pid * (N_ * C_) + (16 * w + r0) * C_;
            const float* pr1 = pr0 + 8 * C_;
            p00 = pr0[2 * c0]; p01 = pr0[2 * c0 + 1];
            p10 = pr1[2 * c0]; p11 = pr1[2 * c0 + 1];
            if (c0 == 0) { p08 = pr0[8]; p18 = pr1[8]; }
            size_t midx = (size_t)pid * N_ + 16 * w + r0;
            if (g_mask4) {
                mk0f = (((const unsigned*)mask)[midx]     != 0u) ? 1.0f : 0.0f;
                mk1f = (((const unsigned*)mask)[midx + 8] != 0u) ? 1.0f : 0.0f;
            } else {
                mk0f = (((const unsigned char*)mask)[midx]     != 0u) ? 1.0f : 0.0f;
                mk1f = (((const unsigned char*)mask)[midx + 8] != 0u) ? 1.0f : 0.0f;
            }
        }
        pa0 = packh2(p00, p01);
        pa1 = packh2(p10, p11);
        pa2 = (c0 == 0) ? packh2(p08, 0.0f) : 0u;
        pa3 = (c0 == 0) ? packh2(p18, 0.0f) : 0u;
        int any = __any_sync(0xFFFFFFFFu, mk0f != 0.0f || mk1f != 0.0f);
        if (lane == 0) sVal2[p * 2 + w] = any;
    }
    const __half2 mk0 = __float2half2_rn(mk0f);
    const __half2 mk1 = __float2half2_rn(mk1f);

    float acc[8][4];
    uint32_t Xa[8], Xb[8];   // X rows r0 / r0+8 packed; A-frags for the next stage

    // ---------------- stage 1: X0 = relu(P @ Wpre' + b0') * mask ----------------
    {
        #pragma unroll
        for (int nt = 0; nt < 8; nt++) {
            int hc = nt * 8 + c0 * 2;
            float v0 = g_b0v[hc], v1 = g_b0v[hc + 1];
            acc[nt][0] = v0; acc[nt][1] = v1;
            acc[nt][2] = v0; acc[nt][3] = v1;
        }
        #pragma unroll
        for (int nt = 0; nt < 8; nt++) {
            uint2 b = *(const uint2*)(g_W0h + nt * 64 + lane * 2);
            mma_f16(acc[nt][0], acc[nt][1], acc[nt][2], acc[nt][3],
                    pa0, pa1, pa2, pa3, b.x, b.y);
        }
        // epilogue: relu*mask, pack to A-frag regs, partial pool
        #pragma unroll
        for (int nt = 0; nt < 8; nt++) {
            Xa[nt] = h2bits(__hmul2(__hmax2(__floats2half2_rn(acc[nt][0], acc[nt][1]), hz), mk0));
            Xb[nt] = h2bits(__hmul2(__hmax2(__floats2half2_rn(acc[nt][2], acc[nt][3]), hz), mk1));
        }
        uint32_t pm[8];
        #pragma unroll
        for (int nt = 0; nt < 8; nt++) pm[nt] = hmax2b(Xa[nt], Xb[nt]);
        #pragma unroll
        for (int s = 4; s < 32; s <<= 1)
            #pragma unroll
            for (int nt = 0; nt < 8; nt++)
                pm[nt] = hmax2b(pm[nt], __shfl_xor_sync(0xFFFFFFFFu, pm[nt], s));
        if (r0 == 0) {
            #pragma unroll
            for (int nt = 0; nt < 8; nt++)
                sPool1h[(p * 2 + w) * PSTR + nt * 4 + c0] = pm[nt];
        }
    }
    __syncthreads();   // pool1 partials visible

    // ---------------- sT = b1' + pooled1 @ W1_hi (fp16, M=4, all 8 warps) ----------------
    // Issued before stage-2 mma; sync deferred until after it (latency hidden).
    {
        const int tw = wid >> 2, tt4 = wid & 3;
        const int hc = wid * 8 + c0 * 2;
        float d0 = g_b1v[hc], d1 = g_b1v[hc + 1], d2 = 0.0f, d3 = 0.0f;
        #pragma unroll
        for (int kt = 0; kt < 4; kt++) {
            uint32_t a0 = 0, a2 = 0;
            if (r0 < 4) {
                a0 = hmax2b(sPool1h[(r0 * 2) * PSTR + kt * 8 + c0],
                            sPool1h[(r0 * 2 + 1) * PSTR + kt * 8 + c0]);
                a2 = hmax2b(sPool1h[(r0 * 2) * PSTR + kt * 8 + 4 + c0],
                            sPool1h[(r0 * 2 + 1) * PSTR + kt * 8 + 4 + c0]);
            }
            uint2 b = *(const uint2*)(g_W1hh + (((tw * 4 + kt) * 4 + tt4) * 32 + lane) * 2);
            mma_f16(d0, d1, d2, d3, a0, 0u, a2, 0u, b.x, b.y);
        }
        if (r0 < 4) {
            sT[r0 * SVW + hc]     = d0;
            sT[r0 * SVW + hc + 1] = d1;
        }
    }

    // ---------------- stage 2 mma: acc = X0 @ W1_lo (A from registers!) ----------------
    {
        #pragma unroll
        for (int nt = 0; nt < 8; nt++) {
            acc[nt][0] = 0.0f; acc[nt][1] = 0.0f;
            acc[nt][2] = 0.0f; acc[nt][3] = 0.0f;
        }
        #pragma unroll
        for (int kt = 0; kt < 4; kt++) {
            uint32_t a0 = Xa[2 * kt], a1 = Xb[2 * kt];
            uint32_t a2 = Xa[2 * kt + 1], a3 = Xb[2 * kt + 1];
            #pragma unroll
            for (int nt = 0; nt < 8; nt++) {
                uint2 b = *(const uint2*)(g_W1h + ((nt >> 2) * 1024 + kt * 256
                                                   + (nt & 3) * 64 + lane * 2));
                mma_f16(acc[nt][0], acc[nt][1], acc[nt][2], acc[nt][3],
                        a0, a1, a2, a3, b.x, b.y);
            }
        }
    }
    __syncthreads();   // sT visible

    // ---------------- stage 2 epilogue: X1 = relu(acc + sT) * mask (registers) ----------------
    {
        #pragma unroll
        for (int nt = 0; nt < 8; nt++) {
            int hc = nt * 8 + c0 * 2;
            float tv0 = sT[p * SVW + hc], tv1 = sT[p * SVW + hc + 1];
            Xa[nt] = h2bits(__hmul2(__hmax2(
                __floats2half2_rn(acc[nt][0] + tv0, acc[nt][1] + tv1), hz), mk0));
            Xb[nt] = h2bits(__hmul2(__hmax2(
                __floats2half2_rn(acc[nt][2] + tv0, acc[nt][3] + tv1), hz), mk1));
        }
    }

    // ---------------- stage 3: relu(X1 @ W2 + b2') * mask -> partial pool ----------------
    {
        #pragma unroll
        for (int nt = 0; nt < 8; nt++) {
            int hc = nt * 8 + c0 * 2;
            float v0 = g_b2v[hc], v1 = g_b2v[hc + 1];
            acc[nt][0] = v0; acc[nt][1] = v1;
            acc[nt][2] = v0; acc[nt][3] = v1;
        }
        #pragma unroll
        for (int kt = 0; kt < 4; kt++) {
            uint32_t a0 = Xa[2 * kt], a1 = Xb[2 * kt];
            uint32_t a2 = Xa[2 * kt + 1], a3 = Xb[2 * kt + 1];
            #pragma unroll
            for (int nt = 0; nt < 8; nt++) {
                uint2 b = *(const uint2*)(g_W2h + ((nt >> 2) * 1024 + kt * 256
                                                   + (nt & 3) * 64 + lane * 2));
                mma_f16(acc[nt][0], acc[nt][1], acc[nt][2], acc[nt][3],
                        a0, a1, a2, a3, b.x, b.y);
            }
        }
        uint32_t pm[8];
        #pragma unroll
        for (int nt = 0; nt < 8; nt++) {
            uint32_t x0 = h2bits(__hmul2(__hmax2(__floats2half2_rn(acc[nt][0], acc[nt][1]), hz), mk0));
            uint32_t x1 = h2bits(__hmul2(__hmax2(__floats2half2_rn(acc[nt][2], acc[nt][3]), hz), mk1));
            pm[nt] = hmax2b(x0, x1);
        }
        #pragma unroll
        for (int s = 4; s < 32; s <<= 1)
            #pragma unroll
            for (int nt = 0; nt < 8; nt++)
                pm[nt] = hmax2b(pm[nt], __shfl_xor_sync(0xFFFFFFFFu, pm[nt], s));
        if (r0 == 0) {
            #pragma unroll
            for (int nt = 0; nt < 8; nt++)
                sPool3h[(p * 2 + w) * PSTR + nt * 4 + c0] = pm[nt];
        }
    }
    __syncthreads();   // pool3 partials visible

    // ---------------- head part 1: H4 = relu(pooled3 @ W3 + b3)  (fp16, M=4) ----------------
    {
        const int tw = wid >> 2, tt4 = wid & 3;
        const int hc = wid * 8 + c0 * 2;
        float d0 = b3[hc], d1 = b3[hc + 1], d2 = 0.0f, d3 = 0.0f;
        #pragma unroll
        for (int kt = 0; kt < 4; kt++) {
            uint32_t a0 = 0, a2 = 0;
            if (r0 < 4) {
                a0 = hmax2b(sPool3h[(r0 * 2) * PSTR + kt * 8 + c0],
                            sPool3h[(r0 * 2 + 1) * PSTR + kt * 8 + c0]);
                a2 = hmax2b(sPool3h[(r0 * 2) * PSTR + kt * 8 + 4 + c0],
                            sPool3h[(r0 * 2 + 1) * PSTR + kt * 8 + 4 + c0]);
            }
            uint2 b = *(const uint2*)(g_W3h + (((tw * 4 + kt) * 4 + tt4) * 32 + lane) * 2);
            mma_f16(d0, d1, d2, d3, a0, 0u, a2, 0u, b.x, b.y);
        }
        if (r0 < 4)
            sH4h[r0 * SVH + wid * 4 + c0] = packh2(fmaxf(d0, 0.0f), fmaxf(d1, 0.0f));
    }
    __syncthreads();

    // ---------------- head part 2: out = (H4 @ W4 + b4) * anyvalid  (fp16, M=4, N=128) ----------------
    {
        const int tt0 = wid * 2;
        float e0[2], e1[2], e2[2], e3[2];
        #pragma unroll
        for (int j = 0; j < 2; j++) {
            int o = (tt0 + j) * 8 + c0 * 2;
            e0[j] = b4[o]; e1[j] = b4[o + 1]; e2[j] = 0.0f; e3[j] = 0.0f;
        }
        #pragma unroll
        for (int kt = 0; kt < 4; kt++) {
            uint32_t a0 = 0, a2 = 0;
            if (r0 < 4) {
                a0 = sH4h[r0 * SVH + kt * 8 + c0];
                a2 = sH4h[r0 * SVH + kt * 8 + 4 + c0];
            }
            #pragma unroll
            for (int j = 0; j < 2; j++) {
                uint2 b = *(const uint2*)(g_W4h + ((kt * 16 + tt0 + j) * 32 + lane) * 2);
                mma_f16(e0[j], e1[j], e2[j], e3[j], a0, 0u, a2, 0u, b.x, b.y);
            }
        }
        if (r0 < 4) {
            float vf = (sVal2[r0 * 2] | sVal2[r0 * 2 + 1]) ? 1.0f : 0.0f;
            #pragma unroll
            for (int j = 0; j < 2; j++) {
                int o = (tt0 + j) * 8 + c0 * 2;
                sOut[r0 * 132 + o]     = e0[j] * vf;
                sOut[r0 * 132 + o + 1] = e1[j] * vf;
            }
        }
    }
    __syncthreads();

    // ---------------- coalesced store ----------------
    if (tid < 128) {
        int pp = tid >> 5, j = tid & 31;
        int opid = blockIdx.x * 4 + pp;
        if (opid < npoly) {
            float4 v = *(const float4*)(sOut + pp * 132 + j * 4);
            *(float4*)(out + (size_t)opid * OUT_ + j * 4) = v;
        }
    }
}

// ============================================================
// Launch
// ============================================================
extern "C" void kernel_launch(void* const* d_in, const int* in_sizes, int n_in,
                              void* d_out, int out_size)
{
    const float* poly = (const float*)d_in[0];
    const float* Wpre = (const float*)d_in[1];
    const float* g0   = (const float*)d_in[2];
    const float* b0   = (const float*)d_in[3];
    const float* m0   = (const float*)d_in[4];
    const float* v0   = (const float*)d_in[5];
    const float* W1   = (const float*)d_in[6];
    const float* g1   = (const float*)d_in[7];
    const float* bb1  = (const float*)d_in[8];
    const float* m1   = (const float*)d_in[9];
    const float* v1   = (const float*)d_in[10];
    const float* W2   = (const float*)d_in[11];
    const float* g2   = (const float*)d_in[12];
    const float* bb2  = (const float*)d_in[13];
    const float* m2   = (const float*)d_in[14];
    const float* v2   = (const float*)d_in[15];
    const float* W3   = (const float*)d_in[16];
    const float* b3   = (const float*)d_in[17];
    const float* W4   = (const float*)d_in[18];
    const float* b4   = (const float*)d_in[19];
    const void*  mask = d_in[20];

    const int npoly = in_sizes[0] / (N_ * C_);

    fold_kernel<<<1, 256>>>(Wpre, g0, b0, m0, v0,
                            W1, g1, bb1, m1, v1,
                            W2, g2, bb2, m2, v2, W3, W4, mask);
    pnet_kernel<<<(npoly + 3) / 4, 256>>>(poly, mask, b3, b4, (float*)d_out, npoly);
}

// round 15
// speedup vs baseline: 1.3797x; 1.0415x over previous
#include <cuda_runtime.h>
#include <cuda_fp16.h>
#include <cstdint>

#define BN_EPS 1e-5f

constexpr int N_    = 32;   // points per polyline
constexpr int C_    = 9;    // input channels
constexpr int H_    = 64;   // hidden
constexpr int OUT_  = 128;
constexpr int PSTR  = 36;   // partial-pool row stride (half2 words)
constexpr int SVH   = 36;   // row stride (half2 words) for H4
constexpr int SVW   = 68;   // row stride (f32) for sT

// -------- device scratch (no allocations allowed) --------
__device__ float    g_b0v[H_], g_b1v[H_], g_b2v[H_];
__device__ uint4    g_W0h4[128];        // folded Wpre, paired-n-tile fp16 B-frags
__device__ uint4    g_W1h4[512];        // folded W1 low half, paired frags
__device__ uint4    g_W2h4[512];        // folded W2, paired frags
__device__ uint4    g_W4h4[1024];       // raw W4 [64][128], paired frags
__device__ uint32_t g_W1hh[2048];       // folded W1 high half, fp16 B-frag (uint2 loads)
__device__ uint32_t g_W3h[2048];        // raw W3, fp16 B-frag (uint2 loads)
__device__ int      g_mask4;            // 1 if mask elements are 4 bytes wide

__device__ __forceinline__ uint32_t packh2(float a, float b) {
    __half2 h = __floats2half2_rn(a, b);
    return *(uint32_t*)&h;
}
__device__ __forceinline__ uint32_t h2bits(__half2 v) { return *(uint32_t*)&v; }
__device__ __forceinline__ __half2  bits2h(uint32_t u) { return *(__half2*)&u; }
__device__ __forceinline__ uint32_t hmax2b(uint32_t a, uint32_t b) {
    return h2bits(__hmax2(bits2h(a), bits2h(b)));
}

__device__ __forceinline__ void mma_f16(float& c0, float& c1, float& c2, float& c3,
                                        uint32_t a0, uint32_t a1, uint32_t a2, uint32_t a3,
                                        uint32_t b0, uint32_t b1) {
    asm volatile(
        "mma.sync.aligned.m16n8k16.row.col.f32.f16.f16.f32 "
        "{%0,%1,%2,%3},{%4,%5,%6,%7},{%8,%9},{%0,%1,%2,%3};\n"
        : "+f"(c0), "+f"(c1), "+f"(c2), "+f"(c3)
        : "r"(a0), "r"(a1), "r"(a2), "r"(a3), "r"(b0), "r"(b1));
}

// ============================================================
// Fold BN into weights, build fp16 B-fragment tables, sniff mask dtype.
// Paired layout: word index = ((grp)*32 + lane)*4 + q*2 + r holds
//   half2 {W[k0][h], W[k0+1][h]} with nt = 2*ntp + q,
//   h = nt*8 + (lane>>2), k0 = kt*16 + (lane&3)*2 + r*8.
// ============================================================
__global__ void fold_kernel(const float* __restrict__ Wpre,
                            const float* __restrict__ g0,  const float* __restrict__ b0,
                            const float* __restrict__ m0,  const float* __restrict__ v0,
                            const float* __restrict__ W1,
                            const float* __restrict__ g1,  const float* __restrict__ bb1,
                            const float* __restrict__ m1,  const float* __restrict__ v1,
                            const float* __restrict__ W2,
                            const float* __restrict__ g2,  const float* __restrict__ bb2,
                            const float* __restrict__ m2,  const float* __restrict__ v2,
                            const float* __restrict__ W3,
                            const float* __restrict__ W4,
                            const void*  __restrict__ mask)
{
    __shared__ float s0[H_], s1[H_], s2[H_];
    __shared__ unsigned red[3];
    const int tid = threadIdx.x;

    if (tid < 3) red[tid] = 0u;
    if (tid < H_) {
        float sc0 = g0[tid] * rsqrtf(v0[tid] + BN_EPS);
        float sc1 = g1[tid] * rsqrtf(v1[tid] + BN_EPS);
        float sc2 = g2[tid] * rsqrtf(v2[tid] + BN_EPS);
        s0[tid] = sc0; s1[tid] = sc1; s2[tid] = sc2;
        g_b0v[tid] = b0[tid]  - m0[tid] * sc0;
        g_b1v[tid] = bb1[tid] - m1[tid] * sc1;
        g_b2v[tid] = bb2[tid] - m2[tid] * sc2;
    }
    __syncthreads();

    // Wpre paired (single kt, C padded to 16): 512 words
    for (int i = tid; i < 512; i += blockDim.x) {
        int r = i & 1, q = (i >> 1) & 1, lane = (i >> 2) & 31, ntp = (i >> 7) & 3;
        int nt = ntp * 2 + q;
        int h  = nt * 8 + (lane >> 2);
        int k0 = (lane & 3) * 2 + r * 8;
        float va = (k0     < C_) ? Wpre[k0 * H_ + h]       * s0[h] : 0.0f;
        float vb = (k0 + 1 < C_) ? Wpre[(k0 + 1) * H_ + h] * s0[h] : 0.0f;
        ((uint32_t*)g_W0h4)[i] = packh2(va, vb);
    }

    // W1 low + W2 paired: kt(4) x ntp(4): 2048 words each
    for (int i = tid; i < 2048; i += blockDim.x) {
        int r = i & 1, q = (i >> 1) & 1, lane = (i >> 2) & 31, ntp = (i >> 7) & 3, kt = (i >> 9) & 3;
        int nt = ntp * 2 + q;
        int h  = nt * 8 + (lane >> 2);
        int k0 = kt * 16 + (lane & 3) * 2 + r * 8;
        ((uint32_t*)g_W1h4)[i] = packh2(W1[k0 * H_ + h] * s1[h], W1[(k0 + 1) * H_ + h] * s1[h]);
        ((uint32_t*)g_W2h4)[i] = packh2(W2[k0 * H_ + h] * s2[h], W2[(k0 + 1) * H_ + h] * s2[h]);
    }

    // W1 high + W3, classic uint2 frag layout (small cooperative GEMMs)
    for (int i = tid; i < 2048; i += blockDim.x) {
        int r = i & 1, lane = (i >> 1) & 31, t = (i >> 6) & 3, kt = (i >> 8) & 3, w = (i >> 10) & 1;
        int k0 = kt * 16 + (lane & 3) * 2 + r * 8;
        int h  = w * 32 + t * 8 + (lane >> 2);
        g_W1hh[i] = packh2(W1[(H_ + k0) * H_ + h] * s1[h], W1[(H_ + k0 + 1) * H_ + h] * s1[h]);
        g_W3h[i]  = packh2(W3[k0 * H_ + h],                W3[(k0 + 1) * H_ + h]);
    }

    // W4 paired: kt(4) x ttp(8): 4096 words
    for (int i = tid; i < 4096; i += blockDim.x) {
        int r = i & 1, q = (i >> 1) & 1, lane = (i >> 2) & 31, ttp = (i >> 7) & 7, kt = (i >> 10) & 3;
        int tt = ttp * 2 + q;
        int o  = tt * 8 + (lane >> 2);
        int k0 = kt * 16 + (lane & 3) * 2 + r * 8;
        ((uint32_t*)g_W4h4)[i] = packh2(W4[k0 * OUT_ + o], W4[(k0 + 1) * OUT_ + o]);
    }

    // Parallel mask dtype sniff (first 1024 bytes).
    {
        const unsigned char* mb = (const unsigned char*)mask;
        unsigned mx = 0, off = 0, al = 0;
        for (int i = tid * 4; i < tid * 4 + 4; i++) {
            unsigned v = mb[i];
            mx |= v;
            if ((i & 3) != 0) off |= v; else al |= v;
        }
        atomicOr(&red[0], mx);
        atomicOr(&red[1], off);
        atomicOr(&red[2], al);
        __syncthreads();
        if (tid == 0)
            g_mask4 = (red[0] > 1u) || (red[1] == 0u && red[2] != 0u);
    }
}

// ============================================================
// Fused encoder, register-resident X chain (R13) + uint4 weight loads.
// 4 polylines per CTA, 256 threads. Warp w of pair p owns point rows
// [16w, 16w+16) across ALL 64 h. C-frag of stage k == A-frag of k+1.
// ============================================================
__global__ __launch_bounds__(256, 4) void pnet_kernel(
    const float* __restrict__ poly,   // [NPOLY, N, C]
    const void*  __restrict__ mask,   // [NPOLY, N]
    const float* __restrict__ b3,     // [H]
    const float* __restrict__ b4,     // [OUT]
    float*       __restrict__ out,    // [NPOLY, OUT]
    int npoly)
{
    __shared__ uint32_t sPool1h[8 * PSTR];   // per-warp partial pool1 [(p*2+w)][32]
    __shared__ uint32_t sPool3h[8 * PSTR];   // per-warp partial pool3
    __shared__ float    sT[4 * SVW];         // stage-2 bias vector per poly
    __shared__ uint32_t sH4h[4 * SVH];       // relu(W3 out) half2 words
    __shared__ __align__(16) float sOut[4 * 132];
    __shared__ int      sVal2[8];            // per-warp any-valid flags

    const int tid  = threadIdx.x;
    const int lane = tid & 31;
    const int wid  = tid >> 5;
    const int p    = wid >> 1;      // poly slot
    const int w    = wid & 1;       // row-half owned by this warp
    const int pid  = blockIdx.x * 4 + p;
    const int r0   = lane >> 2;
    const int c0   = lane & 3;
    const bool vp  = pid < npoly;
    const __half2 hz = __float2half2_rn(0.0f);

    // ---------------- phase 0: points + mask straight into registers ----------------
    uint32_t pa0, pa1, pa2, pa3;    // stage-1 A fragment (C padded to 16)
    float mk0f = 0.0f, mk1f = 0.0f;
    {
        float p00 = 0, p01 = 0, p10 = 0, p11 = 0, p08 = 0, p18 = 0;
        if (vp) {
            const float* pr0 = poly + (size_t)pid * (N_ * C_) + (16 * w + r0) * C_;
            const float* pr1 = pr0 + 8 * C_;
            p00 = pr0[2 * c0]; p01 = pr0[2 * c0 + 1];
            p10 = pr1[2 * c0]; p11 = pr1[2 * c0 + 1];
            if (c0 == 0) { p08 = pr0[8]; p18 = pr1[8]; }
            size_t midx = (size_t)pid * N_ + 16 * w + r0;
            if (g_mask4) {
                mk0f = (((const unsigned*)mask)[midx]     != 0u) ? 1.0f : 0.0f;
                mk1f = (((const unsigned*)mask)[midx + 8] != 0u) ? 1.0f : 0.0f;
            } else {
                mk0f = (((const unsigned char*)mask)[midx]     != 0u) ? 1.0f : 0.0f;
                mk1f = (((const unsigned char*)mask)[midx + 8] != 0u) ? 1.0f : 0.0f;
            }
        }
        pa0 = packh2(p00, p01);
        pa1 = packh2(p10, p11);
        pa2 = (c0 == 0) ? packh2(p08, 0.0f) : 0u;
        pa3 = (c0 == 0) ? packh2(p18, 0.0f) : 0u;
        int any = __any_sync(0xFFFFFFFFu, mk0f != 0.0f || mk1f != 0.0f);
        if (lane == 0) sVal2[p * 2 + w] = any;
    }
    const __half2 mk0 = __float2half2_rn(mk0f);
    const __half2 mk1 = __float2half2_rn(mk1f);

    float acc[8][4];
    uint32_t Xa[8], Xb[8];   // X rows r0 / r0+8 packed; A-frags for the next stage

    // ---------------- stage 1: X0 = relu(P @ Wpre' + b0') * mask ----------------
    {
        #pragma unroll
        for (int nt = 0; nt < 8; nt++) {
            float2 bv = *(const float2*)&g_b0v[nt * 8 + c0 * 2];
            acc[nt][0] = bv.x; acc[nt][1] = bv.y;
            acc[nt][2] = bv.x; acc[nt][3] = bv.y;
        }
        #pragma unroll
        for (int ntp = 0; ntp < 4; ntp++) {
            uint4 b = g_W0h4[ntp * 32 + lane];
            mma_f16(acc[2*ntp][0], acc[2*ntp][1], acc[2*ntp][2], acc[2*ntp][3],
                    pa0, pa1, pa2, pa3, b.x, b.y);
            mma_f16(acc[2*ntp+1][0], acc[2*ntp+1][1], acc[2*ntp+1][2], acc[2*ntp+1][3],
                    pa0, pa1, pa2, pa3, b.z, b.w);
        }
        // epilogue: relu*mask, pack to A-frag regs, partial pool
        #pragma unroll
        for (int nt = 0; nt < 8; nt++) {
            Xa[nt] = h2bits(__hmul2(__hmax2(__floats2half2_rn(acc[nt][0], acc[nt][1]), hz), mk0));
            Xb[nt] = h2bits(__hmul2(__hmax2(__floats2half2_rn(acc[nt][2], acc[nt][3]), hz), mk1));
        }
        uint32_t pm[8];
        #pragma unroll
        for (int nt = 0; nt < 8; nt++) pm[nt] = hmax2b(Xa[nt], Xb[nt]);
        #pragma unroll
        for (int s = 4; s < 32; s <<= 1)
            #pragma unroll
            for (int nt = 0; nt < 8; nt++)
                pm[nt] = hmax2b(pm[nt], __shfl_xor_sync(0xFFFFFFFFu, pm[nt], s));
        if (r0 == 0) {
            #pragma unroll
            for (int nt = 0; nt < 8; nt++)
                sPool1h[(p * 2 + w) * PSTR + nt * 4 + c0] = pm[nt];
        }
    }
    __syncthreads();   // pool1 partials visible

    // ---------------- sT = b1' + pooled1 @ W1_hi (fp16, M=4, all 8 warps) ----------------
    // Issued before stage-2 mma; sync deferred until after it (latency hidden).
    {
        const int tw = wid >> 2, tt4 = wid & 3;
        const int hc = wid * 8 + c0 * 2;
        float2 bv = *(const float2*)&g_b1v[hc];
        float d0 = bv.x, d1 = bv.y, d2 = 0.0f, d3 = 0.0f;
        #pragma unroll
        for (int kt = 0; kt < 4; kt++) {
            uint32_t a0 = 0, a2 = 0;
            if (r0 < 4) {
                a0 = hmax2b(sPool1h[(r0 * 2) * PSTR + kt * 8 + c0],
                            sPool1h[(r0 * 2 + 1) * PSTR + kt * 8 + c0]);
                a2 = hmax2b(sPool1h[(r0 * 2) * PSTR + kt * 8 + 4 + c0],
                            sPool1h[(r0 * 2 + 1) * PSTR + kt * 8 + 4 + c0]);
            }
            uint2 b = *(const uint2*)(g_W1hh + (((tw * 4 + kt) * 4 + tt4) * 32 + lane) * 2);
            mma_f16(d0, d1, d2, d3, a0, 0u, a2, 0u, b.x, b.y);
        }
        if (r0 < 4) {
            sT[r0 * SVW + hc]     = d0;
            sT[r0 * SVW + hc + 1] = d1;
        }
    }

    // ---------------- stage 2 mma: acc = X0 @ W1_lo (A from registers) ----------------
    {
        #pragma unroll
        for (int nt = 0; nt < 8; nt++) {
            acc[nt][0] = 0.0f; acc[nt][1] = 0.0f;
            acc[nt][2] = 0.0f; acc[nt][3] = 0.0f;
        }
        #pragma unroll
        for (int kt = 0; kt < 4; kt++) {
            uint32_t a0 = Xa[2 * kt], a1 = Xb[2 * kt];
            uint32_t a2 = Xa[2 * kt + 1], a3 = Xb[2 * kt + 1];
            #pragma unroll
            for (int ntp = 0; ntp < 4; ntp++) {
                uint4 b = g_W1h4[(kt * 4 + ntp) * 32 + lane];
                mma_f16(acc[2*ntp][0], acc[2*ntp][1], acc[2*ntp][2], acc[2*ntp][3],
                        a0, a1, a2, a3, b.x, b.y);
                mma_f16(acc[2*ntp+1][0], acc[2*ntp+1][1], acc[2*ntp+1][2], acc[2*ntp+1][3],
                        a0, a1, a2, a3, b.z, b.w);
            }
        }
    }
    __syncthreads();   // sT visible

    // ---------------- stage 2 epilogue: X1 = relu(acc + sT) * mask (registers) ----------------
    {
        #pragma unroll
        for (int nt = 0; nt < 8; nt++) {
            float2 tv = *(const float2*)&sT[p * SVW + nt * 8 + c0 * 2];
            Xa[nt] = h2bits(__hmul2(__hmax2(
                __floats2half2_rn(acc[nt][0] + tv.x, acc[nt][1] + tv.y), hz), mk0));
            Xb[nt] = h2bits(__hmul2(__hmax2(
                __floats2half2_rn(acc[nt][2] + tv.x, acc[nt][3] + tv.y), hz), mk1));
        }
    }

    // ---------------- stage 3: relu(X1 @ W2 + b2') * mask -> partial pool ----------------
    {
        #pragma unroll
        for (int nt = 0; nt < 8; nt++) {
            float2 bv = *(const float2*)&g_b2v[nt * 8 + c0 * 2];
            acc[nt][0] = bv.x; acc[nt][1] = bv.y;
            acc[nt][2] = bv.x; acc[nt][3] = bv.y;
        }
        #pragma unroll
        for (int kt = 0; kt < 4; kt++) {
            uint32_t a0 = Xa[2 * kt], a1 = Xb[2 * kt];
            uint32_t a2 = Xa[2 * kt + 1], a3 = Xb[2 * kt + 1];
            #pragma unroll
            for (int ntp = 0; ntp < 4; ntp++) {
                uint4 b = g_W2h4[(kt * 4 + ntp) * 32 + lane];
                mma_f16(acc[2*ntp][0], acc[2*ntp][1], acc[2*ntp][2], acc[2*ntp][3],
                        a0, a1, a2, a3, b.x, b.y);
                mma_f16(acc[2*ntp+1][0], acc[2*ntp+1][1], acc[2*ntp+1][2], acc[2*ntp+1][3],
                        a0, a1, a2, a3, b.z, b.w);
            }
        }
        uint32_t pm[8];
        #pragma unroll
        for (int nt = 0; nt < 8; nt++) {
            uint32_t x0 = h2bits(__hmul2(__hmax2(__floats2half2_rn(acc[nt][0], acc[nt][1]), hz), mk0));
            uint32_t x1 = h2bits(__hmul2(__hmax2(__floats2half2_rn(acc[nt][2], acc[nt][3]), hz), mk1));
            pm[nt] = hmax2b(x0, x1);
        }
        #pragma unroll
        for (int s = 4; s < 32; s <<= 1)
            #pragma unroll
            for (int nt = 0; nt < 8; nt++)
                pm[nt] = hmax2b(pm[nt], __shfl_xor_sync(0xFFFFFFFFu, pm[nt], s));
        if (r0 == 0) {
            #pragma unroll
            for (int nt = 0; nt < 8; nt++)
                sPool3h[(p * 2 + w) * PSTR + nt * 4 + c0] = pm[nt];
        }
    }
    __syncthreads();   // pool3 partials visible

    // ---------------- head part 1: H4 = relu(pooled3 @ W3 + b3)  (fp16, M=4) ----------------
    {
        const int tw = wid >> 2, tt4 = wid & 3;
        const int hc = wid * 8 + c0 * 2;
        float2 bv = *(const float2*)&b3[hc];
        float d0 = bv.x, d1 = bv.y, d2 = 0.0f, d3 = 0.0f;
        #pragma unroll
        for (int kt = 0; kt < 4; kt++) {
            uint32_t a0 = 0, a2 = 0;
            if (r0 < 4) {
                a0 = hmax2b(sPool3h[(r0 * 2) * PSTR + kt * 8 + c0],
                            sPool3h[(r0 * 2 + 1) * PSTR + kt * 8 + c0]);
                a2 = hmax2b(sPool3h[(r0 * 2) * PSTR + kt * 8 + 4 + c0],
                            sPool3h[(r0 * 2 + 1) * PSTR + kt * 8 + 4 + c0]);
            }
            uint2 b = *(const uint2*)(g_W3h + (((tw * 4 + kt) * 4 + tt4) * 32 + lane) * 2);
            mma_f16(d0, d1, d2, d3, a0, 0u, a2, 0u, b.x, b.y);
        }
        if (r0 < 4)
            sH4h[r0 * SVH + wid * 4 + c0] = packh2(fmaxf(d0, 0.0f), fmaxf(d1, 0.0f));
    }
    __syncthreads();

    // ---------------- head part 2: out = (H4 @ W4 + b4) * anyvalid  (fp16, M=4, N=128) ----------------
    {
        const int tt0 = wid * 2;
        float e0[2], e1[2], e2[2], e3[2];
        #pragma unroll
        for (int j = 0; j < 2; j++) {
            float2 bv = *(const float2*)&b4[(tt0 + j) * 8 + c0 * 2];
            e0[j] = bv.x; e1[j] = bv.y; e2[j] = 0.0f; e3[j] = 0.0f;
        }
        #pragma unroll
        for (int kt = 0; kt < 4; kt++) {
            uint32_t a0 = 0, a2 = 0;
            if (r0 < 4) {
                a0 = sH4h[r0 * SVH + kt * 8 + c0];
                a2 = sH4h[r0 * SVH + kt * 8 + 4 + c0];
            }
            uint4 b = g_W4h4[(kt * 8 + wid) * 32 + lane];
            mma_f16(e0[0], e1[0], e2[0], e3[0], a0, 0u, a2, 0u, b.x, b.y);
            mma_f16(e0[1], e1[1], e2[1], e3[1], a0, 0u, a2, 0u, b.z, b.w);
        }
        if (r0 < 4) {
            float vf = (sVal2[r0 * 2] | sVal2[r0 * 2 + 1]) ? 1.0f : 0.0f;
            #pragma unroll
            for (int j = 0; j < 2; j++) {
                int o = (tt0 + j) * 8 + c0 * 2;
                sOut[r0 * 132 + o]     = e0[j] * vf;
                sOut[r0 * 132 + o + 1] = e1[j] * vf;
            }
        }
    }
    __syncthreads();

    // ---------------- coalesced store ----------------
    if (tid < 128) {
        int pp = tid >> 5, j = tid & 31;
        int opid = blockIdx.x * 4 + pp;
        if (opid < npoly) {
            float4 v = *(const float4*)(sOut + pp * 132 + j * 4);
            *(float4*)(out + (size_t)opid * OUT_ + j * 4) = v;
        }
    }
}

// ============================================================
// Launch
// ============================================================
extern "C" void kernel_launch(void* const* d_in, const int* in_sizes, int n_in,
                              void* d_out, int out_size)
{
    const float* poly = (const float*)d_in[0];
    const float* Wpre = (const float*)d_in[1];
    const float* g0   = (const float*)d_in[2];
    const float* b0   = (const float*)d_in[3];
    const float* m0   = (const float*)d_in[4];
    const float* v0   = (const float*)d_in[5];
    const float* W1   = (const float*)d_in[6];
    const float* g1   = (const float*)d_in[7];
    const float* bb1  = (const float*)d_in[8];
    const float* m1   = (const float*)d_in[9];
    const float* v1   = (const float*)d_in[10];
    const float* W2   = (const float*)d_in[11];
    const float* g2   = (const float*)d_in[12];
    const float* bb2  = (const float*)d_in[13];
    const float* m2   = (const float*)d_in[14];
    const float* v2   = (const float*)d_in[15];
    const float* W3   = (const float*)d_in[16];
    const float* b3   = (const float*)d_in[17];
    const float* W4   = (const float*)d_in[18];
    const float* b4   = (const float*)d_in[19];
    const void*  mask = d_in[20];

    const int npoly = in_sizes[0] / (N_ * C_);

    fold_kernel<<<1, 256>>>(Wpre, g0, b0, m0, v0,
                            W1, g1, bb1, m1, v1,
                            W2, g2, bb2, m2, v2, W3, W4, mask);
    pnet_kernel<<<(npoly + 3) / 4, 256>>>(poly, mask, b3, b4, (float*)d_out, npoly);
}